// round 7
// baseline (speedup 1.0000x reference)
#include <cuda_runtime.h>
#include <cuda_bf16.h>
#include <cstdint>

#define ITEM_NUM 100000
#define DIM 64
#define BS 256
#define NC 5

#define M_TILE 128
#define UPC 16                 // users per chunk
#define CHUNKS (BS / UPC)      // 16
#define CGC 2                  // chunks per CTA
#define NBLK (NC * 2)          // 10 n-tiles (8 cols) per chunk
#define THREADS 128
#define NTILES ((ITEM_NUM + M_TILE - 1) / M_TILE)   // 782
#define LOG2E 1.4426950408889634f

// A operand pre-packed in mma fragment order: [tile][tid][32 u32] = 12.8 MB.
__device__ uint32_t g_Af[(size_t)NTILES * THREADS * 32];
// B operand pre-packed in mma B-fragment order: [chunk][nblk][lane][16 bf16] = 160 KB.
__device__ __nv_bfloat16 g_Bf[CHUNKS * NBLK * 32 * 16];

// ---------------- precompute A fragments ----------------
__global__ void precompute_A(const float* __restrict__ item_table) {
    const int bi  = blockIdx.x;
    const int tid = threadIdx.x;
    const int w = tid >> 5, t = tid & 31;
    const int qr = t >> 2, qc = t & 3;
    const int i0 = bi * M_TILE;

    uint32_t frag[32];
    #pragma unroll
    for (int mt = 0; mt < 2; mt++) {
        int r0 = i0 + w * 32 + mt * 16 + qr;
        int r1 = r0 + 8;
        #pragma unroll
        for (int s = 0; s < 4; s++) {
            int k0 = s * 16 + qc * 2;
            float2 x0 = make_float2(0.f, 0.f), x1 = x0, x2 = x0, x3 = x0;
            if (r0 < ITEM_NUM) {
                x0 = *(const float2*)(item_table + (size_t)r0 * DIM + k0);
                x2 = *(const float2*)(item_table + (size_t)r0 * DIM + k0 + 8);
            }
            if (r1 < ITEM_NUM) {
                x1 = *(const float2*)(item_table + (size_t)r1 * DIM + k0);
                x3 = *(const float2*)(item_table + (size_t)r1 * DIM + k0 + 8);
            }
            __nv_bfloat162 b0 = __float22bfloat162_rn(x0);
            __nv_bfloat162 b1 = __float22bfloat162_rn(x1);
            __nv_bfloat162 b2 = __float22bfloat162_rn(x2);
            __nv_bfloat162 b3 = __float22bfloat162_rn(x3);
            frag[(mt * 4 + s) * 4 + 0] = *(uint32_t*)&b0;
            frag[(mt * 4 + s) * 4 + 1] = *(uint32_t*)&b1;
            frag[(mt * 4 + s) * 4 + 2] = *(uint32_t*)&b2;
            frag[(mt * 4 + s) * 4 + 3] = *(uint32_t*)&b3;
        }
    }
    uint4* dst = (uint4*)(g_Af + ((size_t)bi * THREADS + tid) * 32);
    #pragma unroll
    for (int i = 0; i < 8; i++) dst[i] = ((uint4*)frag)[i];
}

// ---------------- precompute B fragments ----------------
// B[n-row = c*16 + uu][k] = user_emb[k] * W[c][k] * log2(e), laid out per-lane:
// slot order matches (b01[0..3], b23[0..3]): k = s*16 + h*8 + (t%4)*2 + e.
__global__ void precompute_Bf(const void* __restrict__ batch_user,
                              const float* __restrict__ user_table,
                              const float* __restrict__ cls_w) {
    const int bi  = blockIdx.x;        // 0..159 = chunk*NBLK + nblk
    const int tid = threadIdx.x;       // 0..511
    const int chunk = bi / NBLK;
    const int nblk  = bi % NBLK;
    const int t    = tid >> 4;         // lane 0..31
    const int slot = tid & 15;

    const int cc = nblk >> 1, g = nblk & 1;
    const int rr = t >> 2;             // B-row within tile = n = t/4
    const int uu = g * 8 + rr;
    const int s = slot >> 2, h = (slot >> 1) & 1, e = slot & 1;
    const int k = s * 16 + h * 8 + (t & 3) * 2 + e;

    const int uslot = chunk * UPC + uu;
    const unsigned* q = (const unsigned*)batch_user;
    bool is64 = ((q[1] | q[3] | q[5] | q[7]) == 0u);
    long long uid = is64 ? ((const long long*)batch_user)[uslot]
                         : (long long)((const int*)batch_user)[uslot];

    g_Bf[(size_t)bi * 512 + tid] =
        __float2bfloat16(user_table[uid * DIM + k] * cls_w[cc * DIM + k] * LOG2E);
}

__device__ __forceinline__ void mma16816(float* d, const uint32_t* a,
                                         uint32_t b0, uint32_t b1) {
    asm volatile(
        "mma.sync.aligned.m16n8k16.row.col.f32.bf16.bf16.f32 "
        "{%0,%1,%2,%3}, {%4,%5,%6,%7}, {%8,%9}, {%0,%1,%2,%3};"
        : "+f"(d[0]), "+f"(d[1]), "+f"(d[2]), "+f"(d[3])
        : "r"(a[0]), "r"(a[1]), "r"(a[2]), "r"(a[3]), "r"(b0), "r"(b1));
}
__device__ __forceinline__ float ex2(float x) {
    float y; asm("ex2.approx.ftz.f32 %0, %1;" : "=f"(y) : "f"(x)); return y;
}
__device__ __forceinline__ float rcpf(float x) {
    float y; asm("rcp.approx.ftz.f32 %0, %1;" : "=f"(y) : "f"(x)); return y;
}

// ---------------- main kernel: no smem, no barriers ----------------
__global__ __launch_bounds__(THREADS, 5) void score_kernel(
    const float* __restrict__ cls_b,
    const float* __restrict__ values,
    float* __restrict__ out)
{
    const int tid = threadIdx.x;
    const int w   = tid >> 5;
    const int t   = tid & 31;
    const int qr  = t >> 2;
    const int qc  = t & 3;
    const int cg  = blockIdx.x;            // chunk-group 0..7
    const int bi  = blockIdx.y;            // item tile 0..781
    const int i0  = bi * M_TILE;

    // ---- A fragments: 8 coalesced LDG.128 ----
    uint32_t afr[32];
    {
        const uint4* ap = (const uint4*)(g_Af + ((size_t)bi * THREADS + tid) * 32);
        #pragma unroll
        for (int i = 0; i < 8; i++) ((uint4*)afr)[i] = __ldg(ap + i);
    }

    // ---- softmax constants (class 0 factored; log2e folded into B & db2) ----
    float v0  = __ldg(values);
    float bb0 = __ldg(cls_b);
    float wc[NC - 1], db2[NC - 1];
    #pragma unroll
    for (int c = 1; c < NC; c++) {
        wc[c - 1]  = __ldg(values + c) - v0;
        db2[c - 1] = (__ldg(cls_b + c) - bb0) * LOG2E;
    }

    // ---- per-thread output byte offsets ----
    char* const outc = (char*)out;
    uint32_t ooff[2][2];
    bool valid[2][2];
    #pragma unroll
    for (int mt = 0; mt < 2; mt++)
        #pragma unroll
        for (int rh = 0; rh < 2; rh++) {
            int gi = i0 + w * 32 + mt * 16 + rh * 8 + qr;
            valid[mt][rh] = (gi < ITEM_NUM);
            ooff[mt][rh] = (uint32_t)((((cg * CGC * UPC) + qc * 2) * ITEM_NUM + gi) * 4);
        }

    #pragma unroll
    for (int j = 0; j < CGC; j++) {
        const int chunk = cg * CGC + j;

        #pragma unroll
        for (int g = 0; g < 2; g++) {
            float acc[2][NC][4];
            #pragma unroll
            for (int mt = 0; mt < 2; mt++)
                #pragma unroll
                for (int cc = 0; cc < NC; cc++)
                    #pragma unroll
                    for (int r = 0; r < 4; r++) acc[mt][cc][r] = 0.f;

            #pragma unroll
            for (int cc = 0; cc < NC; cc++) {
                const int nblk = 2 * cc + g;
                const uint4* bp = (const uint4*)g_Bf
                                  + ((size_t)(chunk * NBLK + nblk) * 32 + t) * 2;
                uint4 q0 = __ldg(bp);
                uint4 q1 = __ldg(bp + 1);
                #pragma unroll
                for (int mt = 0; mt < 2; mt++) {
                    const uint32_t* a = afr + mt * 16;
                    mma16816(acc[mt][cc], a + 0,  q0.x, q0.y);
                    mma16816(acc[mt][cc], a + 4,  q0.z, q0.w);
                    mma16816(acc[mt][cc], a + 8,  q1.x, q1.y);
                    mma16816(acc[mt][cc], a + 12, q1.z, q1.w);
                }
            }

            // ---- fused softmax-EV epilogue (EX2; log2e pre-folded) ----
            #pragma unroll
            for (int mt = 0; mt < 2; mt++)
                #pragma unroll
                for (int rh = 0; rh < 2; rh++) {
                    if (valid[mt][rh]) {
                        #pragma unroll
                        for (int p = 0; p < 2; p++) {
                            const int idx = rh * 2 + p;
                            float l0 = acc[mt][0][idx];
                            float den = 1.f, s = 0.f;
                            #pragma unroll
                            for (int cc = 1; cc < NC; cc++) {
                                float e = ex2(acc[mt][cc][idx] - l0 + db2[cc - 1]);
                                den += e;
                                s = fmaf(e, wc[cc - 1], s);
                            }
                            float res = fmaf(s, rcpf(den), v0);
                            *(float*)(outc + ooff[mt][rh]
                                      + (uint32_t)((g * 8 + p) * ITEM_NUM * 4)) = res;
                        }
                    }
                }
        }

        if (j + 1 < CGC) {
            #pragma unroll
            for (int mt = 0; mt < 2; mt++)
                #pragma unroll
                for (int rh = 0; rh < 2; rh++)
                    ooff[mt][rh] += (uint32_t)(UPC * ITEM_NUM * 4);
        }
    }
}

extern "C" void kernel_launch(void* const* d_in, const int* in_sizes, int n_in,
                              void* d_out, int out_size) {
    const void*  batch_user = d_in[0];
    const float* user_table = (const float*)d_in[1];
    const float* item_table = (const float*)d_in[2];
    const float* cls_w      = (const float*)d_in[3];
    const float* cls_b      = (const float*)d_in[4];
    const float* values     = (const float*)d_in[5];
    float* out = (float*)d_out;

    precompute_A<<<NTILES, THREADS>>>(item_table);
    precompute_Bf<<<CHUNKS * NBLK, 512>>>(batch_user, user_table, cls_w);

    dim3 grid(CHUNKS / CGC, NTILES);   // (8, 782)
    score_kernel<<<grid, THREADS>>>(cls_b, values, out);
}